// round 13
// baseline (speedup 1.0000x reference)
#include <cuda_runtime.h>
#include <cuda_bf16.h>
#include <cstdint>

// ChannelSelfAttention: B=4,H=512,W=256. 2048 independent W x W attentions
// over a 2-channel feature. TWO heads per CTA (grid 1024 x 256 threads);
// each thread owns two query positions of its head. Hot loop = proven R3
// form (MUFU-floor bound, ~90% EX2 duty).
//
// This round: __launch_bounds__(256, 7) squeezes regs 40 -> 36 so SEVEN
// CTAs fit per SM (7*256*36 = 64512 <= 64K regs). 7*148 = 1036 >= 1024
// grid => the ENTIRE grid is one resident wave: the 136-CTA latency-bound
// second wave (the last ~10% of runtime) disappears.

#define W_DIM 256
#define BH_TOTAL 2048
#define PLANE (2048 * 256)

__device__ __forceinline__ uint32_t smem_u32(const void* p) {
    uint32_t a;
    asm("{ .reg .u64 t; cvta.to.shared.u64 t, %1; cvt.u32.u64 %0, t; }"
        : "=r"(a) : "l"(p));
    return a;
}
__device__ __forceinline__ uint64_t pk2(float lo, float hi) {
    uint64_t r; asm("mov.b64 %0, {%1, %2};" : "=l"(r) : "f"(lo), "f"(hi)); return r;
}
__device__ __forceinline__ void upk2(float& lo, float& hi, uint64_t v) {
    asm("mov.b64 {%0, %1}, %2;" : "=f"(lo), "=f"(hi) : "l"(v));
}
__device__ __forceinline__ uint64_t fma2(uint64_t a, uint64_t b, uint64_t c) {
    uint64_t d; asm("fma.rn.f32x2 %0, %1, %2, %3;" : "=l"(d) : "l"(a), "l"(b), "l"(c)); return d;
}
__device__ __forceinline__ uint64_t add2(uint64_t a, uint64_t b) {
    uint64_t d; asm("add.rn.f32x2 %0, %1, %2;" : "=l"(d) : "l"(a), "l"(b)); return d;
}
__device__ __forceinline__ float ex2f(float x) {
    float r; asm("ex2.approx.ftz.f32 %0, %1;" : "=f"(r) : "f"(x)); return r;
}
__device__ __forceinline__ uint64_t mufu_exp2_2(uint64_t p2) {
    float pl, ph; upk2(pl, ph, p2);
    return pk2(ex2f(pl), ex2f(ph));
}

__global__ __launch_bounds__(256, 7) void channel_attn_kernel(
    const float* __restrict__ x1, const float* __restrict__ x2,
    const float* __restrict__ wq, const float* __restrict__ bq,
    const float* __restrict__ wk, const float* __restrict__ bk,
    const float* __restrict__ wv, const float* __restrict__ bv,
    float* __restrict__ out)
{
    const int tid  = threadIdx.x;
    const int head = tid >> 7;          // 0 or 1 within this CTA
    const int t    = tid & 127;         // lane within head
    const int base = (blockIdx.x * 2 + head) * W_DIM;

    __shared__ __align__(16) float kArr[2][2 * W_DIM];
    __shared__ __align__(16) float vArr[2][2 * W_DIM];
    __shared__ float red[16];

    const float aA = x1[base + t];
    const float bA = x2[base + t];
    const float aB = x1[base + t + 128];
    const float bB = x2[base + t + 128];

    const float w_q0 = wq[0], w_q1 = wq[1], w_q2 = wq[2], w_q3 = wq[3];
    const float w_k0 = wk[0], w_k1 = wk[1], w_k2 = wk[2], w_k3 = wk[3];
    const float w_v0 = wv[0], w_v1 = wv[1], w_v2 = wv[2], w_v3 = wv[3];
    const float b_q0 = bq[0], b_q1 = bq[1];
    const float b_k0 = bk[0], b_k1 = bk[1];
    const float b_v0 = bv[0], b_v1 = bv[1];

    const float qA0 = fmaf(w_q0, aA, fmaf(w_q1, bA, b_q0));
    const float qA1 = fmaf(w_q2, aA, fmaf(w_q3, bA, b_q1));
    const float kA0 = fmaf(w_k0, aA, fmaf(w_k1, bA, b_k0));
    const float kA1 = fmaf(w_k2, aA, fmaf(w_k3, bA, b_k1));
    const float vA0 = fmaf(w_v0, aA, fmaf(w_v1, bA, b_v0));
    const float vA1 = fmaf(w_v2, aA, fmaf(w_v3, bA, b_v1));

    const float qB0 = fmaf(w_q0, aB, fmaf(w_q1, bB, b_q0));
    const float qB1 = fmaf(w_q2, aB, fmaf(w_q3, bB, b_q1));
    const float kB0 = fmaf(w_k0, aB, fmaf(w_k1, bB, b_k0));
    const float kB1 = fmaf(w_k2, aB, fmaf(w_k3, bB, b_k1));
    const float vB0 = fmaf(w_v0, aB, fmaf(w_v1, bB, b_v0));
    const float vB1 = fmaf(w_v2, aB, fmaf(w_v3, bB, b_v1));

    {
        int j = t >> 1, h = t & 1;
        kArr[head][4 * j + h] = kA0;  kArr[head][4 * j + 2 + h] = kA1;
        vArr[head][4 * j + h] = vA0;  vArr[head][4 * j + 2 + h] = vA1;
        int w2 = t + 128;
        j = w2 >> 1; h = w2 & 1;
        kArr[head][4 * j + h] = kB0;  kArr[head][4 * j + 2 + h] = kB1;
        vArr[head][4 * j + h] = vB0;  vArr[head][4 * j + 2 + h] = vB1;
    }

    float ak0 = fmaxf(fabsf(kA0), fabsf(kB0));
    float ak1 = fmaxf(fabsf(kA1), fabsf(kB1));
#pragma unroll
    for (int o = 16; o; o >>= 1) {
        ak0 = fmaxf(ak0, __shfl_xor_sync(0xffffffffu, ak0, o));
        ak1 = fmaxf(ak1, __shfl_xor_sync(0xffffffffu, ak1, o));
    }
    const int wh = (tid >> 5) & 3;
    if ((tid & 31) == 0) { red[head * 8 + wh] = ak0; red[head * 8 + 4 + wh] = ak1; }
    __syncthreads();

    const float* rh = &red[head * 8];
    float mk0 = fmaxf(fmaxf(rh[0], rh[1]), fmaxf(rh[2], rh[3]));
    float mk1 = fmaxf(fmaxf(rh[4], rh[5]), fmaxf(rh[6], rh[7]));

    const float L2E = 1.4426950408889634f;
    const float qA0e = qA0 * L2E, qA1e = qA1 * L2E;
    const float qB0e = qB0 * L2E, qB1e = qB1 * L2E;
    const float mhatA = fmaf(fabsf(qA0e), mk0, fabsf(qA1e) * mk1);
    const float mhatB = fmaf(fabsf(qB0e), mk0, fabsf(qB1e) * mk1);

    const uint64_t qA0_2 = pk2(qA0e, qA0e), qA1_2 = pk2(qA1e, qA1e);
    const uint64_t qB0_2 = pk2(qB0e, qB0e), qB1_2 = pk2(qB1e, qB1e);
    const uint64_t mnA2 = pk2(-mhatA, -mhatA), mnB2 = pk2(-mhatB, -mhatB);

    uint64_t sumA = 0ull, accA0 = 0ull, accA1 = 0ull;
    uint64_t sumB = 0ull, accB0 = 0ull, accB1 = 0ull;

    const uint32_t kb = smem_u32(&kArr[head][0]);
    const uint32_t vb = smem_u32(&vArr[head][0]);

#pragma unroll 4
    for (int qd = 0; qd < W_DIM / 4; ++qd) {  // 4 keys per iteration
        uint64_t K0a, K0b, K1a, K1b, V0a, V0b, V1a, V1b;
        asm("ld.shared.v2.u64 {%0, %1}, [%2];"
            : "=l"(K0a), "=l"(K0b) : "r"(kb + 32u * qd));
        asm("ld.shared.v2.u64 {%0, %1}, [%2];"
            : "=l"(K1a), "=l"(K1b) : "r"(kb + 32u * qd + 16u));
        asm("ld.shared.v2.u64 {%0, %1}, [%2];"
            : "=l"(V0a), "=l"(V0b) : "r"(vb + 32u * qd));
        asm("ld.shared.v2.u64 {%0, %1}, [%2];"
            : "=l"(V1a), "=l"(V1b) : "r"(vb + 32u * qd + 16u));

        const uint64_t pA0 = fma2(qA0_2, K0a, fma2(qA1_2, K0b, mnA2));
        const uint64_t pA1 = fma2(qA0_2, K1a, fma2(qA1_2, K1b, mnA2));
        const uint64_t pB0 = fma2(qB0_2, K0a, fma2(qB1_2, K0b, mnB2));
        const uint64_t pB1 = fma2(qB0_2, K1a, fma2(qB1_2, K1b, mnB2));

        const uint64_t eA0 = mufu_exp2_2(pA0);
        const uint64_t eA1 = mufu_exp2_2(pA1);
        const uint64_t eB0 = mufu_exp2_2(pB0);
        const uint64_t eB1 = mufu_exp2_2(pB1);

        sumA = add2(sumA, add2(eA0, eA1));
        sumB = add2(sumB, add2(eB0, eB1));
        accA0 = fma2(eA0, V0a, accA0);
        accA0 = fma2(eA1, V1a, accA0);
        accA1 = fma2(eA0, V0b, accA1);
        accA1 = fma2(eA1, V1b, accA1);
        accB0 = fma2(eB0, V0a, accB0);
        accB0 = fma2(eB1, V1a, accB0);
        accB1 = fma2(eB0, V0b, accB1);
        accB1 = fma2(eB1, V1b, accB1);
    }

    float sl, sh, x0l, x0h, x1l, x1h;
    float invA, invB;

    upk2(sl, sh, sumA);
    asm("rcp.approx.ftz.f32 %0, %1;" : "=f"(invA) : "f"(sl + sh));
    upk2(sl, sh, sumB);
    asm("rcp.approx.ftz.f32 %0, %1;" : "=f"(invB) : "f"(sl + sh));

    upk2(x0l, x0h, accA0);
    upk2(x1l, x1h, accA1);
    out[base + t]          = fmaf(x0l + x0h, invA, aA);
    out[PLANE + base + t]  = fmaf(x1l + x1h, invA, bA);

    upk2(x0l, x0h, accB0);
    upk2(x1l, x1h, accB1);
    out[base + t + 128]         = fmaf(x0l + x0h, invB, aB);
    out[PLANE + base + t + 128] = fmaf(x1l + x1h, invB, bB);
}

extern "C" void kernel_launch(void* const* d_in, const int* in_sizes, int n_in,
                              void* d_out, int out_size)
{
    (void)in_sizes; (void)n_in; (void)out_size;
    channel_attn_kernel<<<BH_TOTAL / 2, 256>>>(
        (const float*)d_in[0], (const float*)d_in[1],
        (const float*)d_in[2], (const float*)d_in[3],
        (const float*)d_in[4], (const float*)d_in[5],
        (const float*)d_in[6], (const float*)d_in[7],
        (float*)d_out);
}

// round 14
// speedup vs baseline: 1.2343x; 1.2343x over previous
#include <cuda_runtime.h>
#include <cuda_bf16.h>
#include <cstdint>

// ChannelSelfAttention: B=4,H=512,W=256. 2048 independent W x W attentions
// over a 2-channel feature. FINAL kernel (best measured: 33.2us dur).
//
// Design (validated over 13 rounds):
//  - Two heads per CTA (grid 1024 x 256 threads); threads 0-127 -> head
//    2*blk, threads 128-255 -> head 2*blk+1; each thread owns two query
//    positions of its head (halves broadcast-LDS traffic).
//  - Single-pass softmax with overflow-safe upper bound m_hat (softmax is
//    shift-invariant; bound from per-head max|k| needs no exact row max).
//  - All inner math packed f32x2 (FFMA2, 2 keys/op); exps on f32 MUFU EX2.
//  - Runs at ~89% of the chip-wide EX2 throughput floor. Measured dead
//    ends: FMA-pipe poly exp (latency-chain bound), f16x2 exp (no native
//    f16 MUFU; converts share the xu pipe), minblocks 7 (32-reg granule
//    forces hot-loop spills), higher occupancy (MUFU duty already ~90%).

#define W_DIM 256
#define BH_TOTAL 2048
#define PLANE (2048 * 256)

__device__ __forceinline__ uint32_t smem_u32(const void* p) {
    uint32_t a;
    asm("{ .reg .u64 t; cvta.to.shared.u64 t, %1; cvt.u32.u64 %0, t; }"
        : "=r"(a) : "l"(p));
    return a;
}
__device__ __forceinline__ uint64_t pk2(float lo, float hi) {
    uint64_t r; asm("mov.b64 %0, {%1, %2};" : "=l"(r) : "f"(lo), "f"(hi)); return r;
}
__device__ __forceinline__ void upk2(float& lo, float& hi, uint64_t v) {
    asm("mov.b64 {%0, %1}, %2;" : "=f"(lo), "=f"(hi) : "l"(v));
}
__device__ __forceinline__ uint64_t fma2(uint64_t a, uint64_t b, uint64_t c) {
    uint64_t d; asm("fma.rn.f32x2 %0, %1, %2, %3;" : "=l"(d) : "l"(a), "l"(b), "l"(c)); return d;
}
__device__ __forceinline__ uint64_t add2(uint64_t a, uint64_t b) {
    uint64_t d; asm("add.rn.f32x2 %0, %1, %2;" : "=l"(d) : "l"(a), "l"(b)); return d;
}
__device__ __forceinline__ float ex2f(float x) {
    float r; asm("ex2.approx.ftz.f32 %0, %1;" : "=f"(r) : "f"(x)); return r;
}
__device__ __forceinline__ uint64_t mufu_exp2_2(uint64_t p2) {
    float pl, ph; upk2(pl, ph, p2);
    return pk2(ex2f(pl), ex2f(ph));
}

__global__ __launch_bounds__(256) void channel_attn_kernel(
    const float* __restrict__ x1, const float* __restrict__ x2,
    const float* __restrict__ wq, const float* __restrict__ bq,
    const float* __restrict__ wk, const float* __restrict__ bk,
    const float* __restrict__ wv, const float* __restrict__ bv,
    float* __restrict__ out)
{
    const int tid  = threadIdx.x;
    const int head = tid >> 7;          // 0 or 1 within this CTA
    const int t    = tid & 127;         // lane within head
    const int base = (blockIdx.x * 2 + head) * W_DIM;

    // Per-head pairwise SoA: pair j holds (k0[2j],k0[2j+1],k1[2j],k1[2j+1])
    __shared__ __align__(16) float kArr[2][2 * W_DIM];
    __shared__ __align__(16) float vArr[2][2 * W_DIM];
    __shared__ float red[16];           // [head*8 + {0..3}: ak0, {4..7}: ak1]

    const float aA = x1[base + t];
    const float bA = x2[base + t];
    const float aB = x1[base + t + 128];
    const float bB = x2[base + t + 128];

    const float w_q0 = wq[0], w_q1 = wq[1], w_q2 = wq[2], w_q3 = wq[3];
    const float w_k0 = wk[0], w_k1 = wk[1], w_k2 = wk[2], w_k3 = wk[3];
    const float w_v0 = wv[0], w_v1 = wv[1], w_v2 = wv[2], w_v3 = wv[3];
    const float b_q0 = bq[0], b_q1 = bq[1];
    const float b_k0 = bk[0], b_k1 = bk[1];
    const float b_v0 = bv[0], b_v1 = bv[1];

    const float qA0 = fmaf(w_q0, aA, fmaf(w_q1, bA, b_q0));
    const float qA1 = fmaf(w_q2, aA, fmaf(w_q3, bA, b_q1));
    const float kA0 = fmaf(w_k0, aA, fmaf(w_k1, bA, b_k0));
    const float kA1 = fmaf(w_k2, aA, fmaf(w_k3, bA, b_k1));
    const float vA0 = fmaf(w_v0, aA, fmaf(w_v1, bA, b_v0));
    const float vA1 = fmaf(w_v2, aA, fmaf(w_v3, bA, b_v1));

    const float qB0 = fmaf(w_q0, aB, fmaf(w_q1, bB, b_q0));
    const float qB1 = fmaf(w_q2, aB, fmaf(w_q3, bB, b_q1));
    const float kB0 = fmaf(w_k0, aB, fmaf(w_k1, bB, b_k0));
    const float kB1 = fmaf(w_k2, aB, fmaf(w_k3, bB, b_k1));
    const float vB0 = fmaf(w_v0, aB, fmaf(w_v1, bB, b_v0));
    const float vB1 = fmaf(w_v2, aB, fmaf(w_v3, bB, b_v1));

    {
        int j = t >> 1, h = t & 1;
        kArr[head][4 * j + h] = kA0;  kArr[head][4 * j + 2 + h] = kA1;
        vArr[head][4 * j + h] = vA0;  vArr[head][4 * j + 2 + h] = vA1;
        int w2 = t + 128;
        j = w2 >> 1; h = w2 & 1;
        kArr[head][4 * j + h] = kB0;  kArr[head][4 * j + 2 + h] = kB1;
        vArr[head][4 * j + h] = vB0;  vArr[head][4 * j + 2 + h] = vB1;
    }

    // per-head max|k0|, max|k1| for the overflow-safe softmax bound
    float ak0 = fmaxf(fabsf(kA0), fabsf(kB0));
    float ak1 = fmaxf(fabsf(kA1), fabsf(kB1));
#pragma unroll
    for (int o = 16; o; o >>= 1) {
        ak0 = fmaxf(ak0, __shfl_xor_sync(0xffffffffu, ak0, o));
        ak1 = fmaxf(ak1, __shfl_xor_sync(0xffffffffu, ak1, o));
    }
    const int wh = (tid >> 5) & 3;      // warp index within head (0..3)
    if ((tid & 31) == 0) { red[head * 8 + wh] = ak0; red[head * 8 + 4 + wh] = ak1; }
    __syncthreads();

    const float* rh = &red[head * 8];
    float mk0 = fmaxf(fmaxf(rh[0], rh[1]), fmaxf(rh[2], rh[3]));
    float mk1 = fmaxf(fmaxf(rh[4], rh[5]), fmaxf(rh[6], rh[7]));

    const float L2E = 1.4426950408889634f;
    const float qA0e = qA0 * L2E, qA1e = qA1 * L2E;
    const float qB0e = qB0 * L2E, qB1e = qB1 * L2E;
    const float mhatA = fmaf(fabsf(qA0e), mk0, fabsf(qA1e) * mk1);
    const float mhatB = fmaf(fabsf(qB0e), mk0, fabsf(qB1e) * mk1);

    const uint64_t qA0_2 = pk2(qA0e, qA0e), qA1_2 = pk2(qA1e, qA1e);
    const uint64_t qB0_2 = pk2(qB0e, qB0e), qB1_2 = pk2(qB1e, qB1e);
    const uint64_t mnA2 = pk2(-mhatA, -mhatA), mnB2 = pk2(-mhatB, -mhatB);

    uint64_t sumA = 0ull, accA0 = 0ull, accA1 = 0ull;
    uint64_t sumB = 0ull, accB0 = 0ull, accB1 = 0ull;

    const uint32_t kb = smem_u32(&kArr[head][0]);
    const uint32_t vb = smem_u32(&vArr[head][0]);

#pragma unroll 4
    for (int qd = 0; qd < W_DIM / 4; ++qd) {  // 4 keys per iteration
        uint64_t K0a, K0b, K1a, K1b, V0a, V0b, V1a, V1b;
        asm("ld.shared.v2.u64 {%0, %1}, [%2];"
            : "=l"(K0a), "=l"(K0b) : "r"(kb + 32u * qd));
        asm("ld.shared.v2.u64 {%0, %1}, [%2];"
            : "=l"(K1a), "=l"(K1b) : "r"(kb + 32u * qd + 16u));
        asm("ld.shared.v2.u64 {%0, %1}, [%2];"
            : "=l"(V0a), "=l"(V0b) : "r"(vb + 32u * qd));
        asm("ld.shared.v2.u64 {%0, %1}, [%2];"
            : "=l"(V1a), "=l"(V1b) : "r"(vb + 32u * qd + 16u));

        const uint64_t pA0 = fma2(qA0_2, K0a, fma2(qA1_2, K0b, mnA2));
        const uint64_t pA1 = fma2(qA0_2, K1a, fma2(qA1_2, K1b, mnA2));
        const uint64_t pB0 = fma2(qB0_2, K0a, fma2(qB1_2, K0b, mnB2));
        const uint64_t pB1 = fma2(qB0_2, K1a, fma2(qB1_2, K1b, mnB2));

        const uint64_t eA0 = mufu_exp2_2(pA0);
        const uint64_t eA1 = mufu_exp2_2(pA1);
        const uint64_t eB0 = mufu_exp2_2(pB0);
        const uint64_t eB1 = mufu_exp2_2(pB1);

        sumA = add2(sumA, add2(eA0, eA1));
        sumB = add2(sumB, add2(eB0, eB1));
        accA0 = fma2(eA0, V0a, accA0);
        accA0 = fma2(eA1, V1a, accA0);
        accA1 = fma2(eA0, V0b, accA1);
        accA1 = fma2(eA1, V1b, accA1);
        accB0 = fma2(eB0, V0a, accB0);
        accB0 = fma2(eB1, V1a, accB0);
        accB1 = fma2(eB0, V0b, accB1);
        accB1 = fma2(eB1, V1b, accB1);
    }

    float sl, sh, x0l, x0h, x1l, x1h;
    float invA, invB;

    upk2(sl, sh, sumA);
    asm("rcp.approx.ftz.f32 %0, %1;" : "=f"(invA) : "f"(sl + sh));
    upk2(sl, sh, sumB);
    asm("rcp.approx.ftz.f32 %0, %1;" : "=f"(invB) : "f"(sl + sh));

    upk2(x0l, x0h, accA0);
    upk2(x1l, x1h, accA1);
    out[base + t]          = fmaf(x0l + x0h, invA, aA);
    out[PLANE + base + t]  = fmaf(x1l + x1h, invA, bA);

    upk2(x0l, x0h, accB0);
    upk2(x1l, x1h, accB1);
    out[base + t + 128]         = fmaf(x0l + x0h, invB, aB);
    out[PLANE + base + t + 128] = fmaf(x1l + x1h, invB, bB);
}

extern "C" void kernel_launch(void* const* d_in, const int* in_sizes, int n_in,
                              void* d_out, int out_size)
{
    (void)in_sizes; (void)n_in; (void)out_size;
    channel_attn_kernel<<<BH_TOTAL / 2, 256>>>(
        (const float*)d_in[0], (const float*)d_in[1],
        (const float*)d_in[2], (const float*)d_in[3],
        (const float*)d_in[4], (const float*)d_in[5],
        (const float*)d_in[6], (const float*)d_in[7],
        (float*)d_out);
}

// round 15
// speedup vs baseline: 1.2474x; 1.0106x over previous
#include <cuda_runtime.h>
#include <cuda_bf16.h>
#include <cstdint>

// ChannelSelfAttention: B=4,H=512,W=256. 2048 independent W x W attentions
// over a 2-channel feature. FINAL kernel (best measured: 33.2us dur).
//
// Design (validated over 13 rounds):
//  - Two heads per CTA (grid 1024 x 256 threads); threads 0-127 -> head
//    2*blk, threads 128-255 -> head 2*blk+1; each thread owns two query
//    positions of its head (halves broadcast-LDS traffic).
//  - Single-pass softmax with overflow-safe upper bound m_hat (softmax is
//    shift-invariant; bound from per-head max|k| needs no exact row max).
//  - All inner math packed f32x2 (FFMA2, 2 keys/op); exps on f32 MUFU EX2.
//  - Runs at ~89% of the chip-wide EX2 throughput floor. Measured dead
//    ends: FMA-pipe poly exp (latency-chain bound), f16x2 exp (no native
//    f16 MUFU; converts share the xu pipe), minblocks 7 (32-reg granule
//    forces hot-loop spills), higher occupancy (MUFU duty already ~90%).

#define W_DIM 256
#define BH_TOTAL 2048
#define PLANE (2048 * 256)

__device__ __forceinline__ uint32_t smem_u32(const void* p) {
    uint32_t a;
    asm("{ .reg .u64 t; cvta.to.shared.u64 t, %1; cvt.u32.u64 %0, t; }"
        : "=r"(a) : "l"(p));
    return a;
}
__device__ __forceinline__ uint64_t pk2(float lo, float hi) {
    uint64_t r; asm("mov.b64 %0, {%1, %2};" : "=l"(r) : "f"(lo), "f"(hi)); return r;
}
__device__ __forceinline__ void upk2(float& lo, float& hi, uint64_t v) {
    asm("mov.b64 {%0, %1}, %2;" : "=f"(lo), "=f"(hi) : "l"(v));
}
__device__ __forceinline__ uint64_t fma2(uint64_t a, uint64_t b, uint64_t c) {
    uint64_t d; asm("fma.rn.f32x2 %0, %1, %2, %3;" : "=l"(d) : "l"(a), "l"(b), "l"(c)); return d;
}
__device__ __forceinline__ uint64_t add2(uint64_t a, uint64_t b) {
    uint64_t d; asm("add.rn.f32x2 %0, %1, %2;" : "=l"(d) : "l"(a), "l"(b)); return d;
}
__device__ __forceinline__ float ex2f(float x) {
    float r; asm("ex2.approx.ftz.f32 %0, %1;" : "=f"(r) : "f"(x)); return r;
}
__device__ __forceinline__ uint64_t mufu_exp2_2(uint64_t p2) {
    float pl, ph; upk2(pl, ph, p2);
    return pk2(ex2f(pl), ex2f(ph));
}

__global__ __launch_bounds__(256) void channel_attn_kernel(
    const float* __restrict__ x1, const float* __restrict__ x2,
    const float* __restrict__ wq, const float* __restrict__ bq,
    const float* __restrict__ wk, const float* __restrict__ bk,
    const float* __restrict__ wv, const float* __restrict__ bv,
    float* __restrict__ out)
{
    const int tid  = threadIdx.x;
    const int head = tid >> 7;          // 0 or 1 within this CTA
    const int t    = tid & 127;         // lane within head
    const int base = (blockIdx.x * 2 + head) * W_DIM;

    // Per-head pairwise SoA: pair j holds (k0[2j],k0[2j+1],k1[2j],k1[2j+1])
    __shared__ __align__(16) float kArr[2][2 * W_DIM];
    __shared__ __align__(16) float vArr[2][2 * W_DIM];
    __shared__ float red[16];           // [head*8 + {0..3}: ak0, {4..7}: ak1]

    const float aA = x1[base + t];
    const float bA = x2[base + t];
    const float aB = x1[base + t + 128];
    const float bB = x2[base + t + 128];

    const float w_q0 = wq[0], w_q1 = wq[1], w_q2 = wq[2], w_q3 = wq[3];
    const float w_k0 = wk[0], w_k1 = wk[1], w_k2 = wk[2], w_k3 = wk[3];
    const float w_v0 = wv[0], w_v1 = wv[1], w_v2 = wv[2], w_v3 = wv[3];
    const float b_q0 = bq[0], b_q1 = bq[1];
    const float b_k0 = bk[0], b_k1 = bk[1];
    const float b_v0 = bv[0], b_v1 = bv[1];

    const float qA0 = fmaf(w_q0, aA, fmaf(w_q1, bA, b_q0));
    const float qA1 = fmaf(w_q2, aA, fmaf(w_q3, bA, b_q1));
    const float kA0 = fmaf(w_k0, aA, fmaf(w_k1, bA, b_k0));
    const float kA1 = fmaf(w_k2, aA, fmaf(w_k3, bA, b_k1));
    const float vA0 = fmaf(w_v0, aA, fmaf(w_v1, bA, b_v0));
    const float vA1 = fmaf(w_v2, aA, fmaf(w_v3, bA, b_v1));

    const float qB0 = fmaf(w_q0, aB, fmaf(w_q1, bB, b_q0));
    const float qB1 = fmaf(w_q2, aB, fmaf(w_q3, bB, b_q1));
    const float kB0 = fmaf(w_k0, aB, fmaf(w_k1, bB, b_k0));
    const float kB1 = fmaf(w_k2, aB, fmaf(w_k3, bB, b_k1));
    const float vB0 = fmaf(w_v0, aB, fmaf(w_v1, bB, b_v0));
    const float vB1 = fmaf(w_v2, aB, fmaf(w_v3, bB, b_v1));

    {
        int j = t >> 1, h = t & 1;
        kArr[head][4 * j + h] = kA0;  kArr[head][4 * j + 2 + h] = kA1;
        vArr[head][4 * j + h] = vA0;  vArr[head][4 * j + 2 + h] = vA1;
        int w2 = t + 128;
        j = w2 >> 1; h = w2 & 1;
        kArr[head][4 * j + h] = kB0;  kArr[head][4 * j + 2 + h] = kB1;
        vArr[head][4 * j + h] = vB0;  vArr[head][4 * j + 2 + h] = vB1;
    }

    // per-head max|k0|, max|k1| for the overflow-safe softmax bound
    float ak0 = fmaxf(fabsf(kA0), fabsf(kB0));
    float ak1 = fmaxf(fabsf(kA1), fabsf(kB1));
#pragma unroll
    for (int o = 16; o; o >>= 1) {
        ak0 = fmaxf(ak0, __shfl_xor_sync(0xffffffffu, ak0, o));
        ak1 = fmaxf(ak1, __shfl_xor_sync(0xffffffffu, ak1, o));
    }
    const int wh = (tid >> 5) & 3;      // warp index within head (0..3)
    if ((tid & 31) == 0) { red[head * 8 + wh] = ak0; red[head * 8 + 4 + wh] = ak1; }
    __syncthreads();

    const float* rh = &red[head * 8];
    float mk0 = fmaxf(fmaxf(rh[0], rh[1]), fmaxf(rh[2], rh[3]));
    float mk1 = fmaxf(fmaxf(rh[4], rh[5]), fmaxf(rh[6], rh[7]));

    const float L2E = 1.4426950408889634f;
    const float qA0e = qA0 * L2E, qA1e = qA1 * L2E;
    const float qB0e = qB0 * L2E, qB1e = qB1 * L2E;
    const float mhatA = fmaf(fabsf(qA0e), mk0, fabsf(qA1e) * mk1);
    const float mhatB = fmaf(fabsf(qB0e), mk0, fabsf(qB1e) * mk1);

    const uint64_t qA0_2 = pk2(qA0e, qA0e), qA1_2 = pk2(qA1e, qA1e);
    const uint64_t qB0_2 = pk2(qB0e, qB0e), qB1_2 = pk2(qB1e, qB1e);
    const uint64_t mnA2 = pk2(-mhatA, -mhatA), mnB2 = pk2(-mhatB, -mhatB);

    uint64_t sumA = 0ull, accA0 = 0ull, accA1 = 0ull;
    uint64_t sumB = 0ull, accB0 = 0ull, accB1 = 0ull;

    const uint32_t kb = smem_u32(&kArr[head][0]);
    const uint32_t vb = smem_u32(&vArr[head][0]);

#pragma unroll 4
    for (int qd = 0; qd < W_DIM / 4; ++qd) {  // 4 keys per iteration
        uint64_t K0a, K0b, K1a, K1b, V0a, V0b, V1a, V1b;
        asm("ld.shared.v2.u64 {%0, %1}, [%2];"
            : "=l"(K0a), "=l"(K0b) : "r"(kb + 32u * qd));
        asm("ld.shared.v2.u64 {%0, %1}, [%2];"
            : "=l"(K1a), "=l"(K1b) : "r"(kb + 32u * qd + 16u));
        asm("ld.shared.v2.u64 {%0, %1}, [%2];"
            : "=l"(V0a), "=l"(V0b) : "r"(vb + 32u * qd));
        asm("ld.shared.v2.u64 {%0, %1}, [%2];"
            : "=l"(V1a), "=l"(V1b) : "r"(vb + 32u * qd + 16u));

        const uint64_t pA0 = fma2(qA0_2, K0a, fma2(qA1_2, K0b, mnA2));
        const uint64_t pA1 = fma2(qA0_2, K1a, fma2(qA1_2, K1b, mnA2));
        const uint64_t pB0 = fma2(qB0_2, K0a, fma2(qB1_2, K0b, mnB2));
        const uint64_t pB1 = fma2(qB0_2, K1a, fma2(qB1_2, K1b, mnB2));

        const uint64_t eA0 = mufu_exp2_2(pA0);
        const uint64_t eA1 = mufu_exp2_2(pA1);
        const uint64_t eB0 = mufu_exp2_2(pB0);
        const uint64_t eB1 = mufu_exp2_2(pB1);

        sumA = add2(sumA, add2(eA0, eA1));
        sumB = add2(sumB, add2(eB0, eB1));
        accA0 = fma2(eA0, V0a, accA0);
        accA0 = fma2(eA1, V1a, accA0);
        accA1 = fma2(eA0, V0b, accA1);
        accA1 = fma2(eA1, V1b, accA1);
        accB0 = fma2(eB0, V0a, accB0);
        accB0 = fma2(eB1, V1a, accB0);
        accB1 = fma2(eB0, V0b, accB1);
        accB1 = fma2(eB1, V1b, accB1);
    }

    float sl, sh, x0l, x0h, x1l, x1h;
    float invA, invB;

    upk2(sl, sh, sumA);
    asm("rcp.approx.ftz.f32 %0, %1;" : "=f"(invA) : "f"(sl + sh));
    upk2(sl, sh, sumB);
    asm("rcp.approx.ftz.f32 %0, %1;" : "=f"(invB) : "f"(sl + sh));

    upk2(x0l, x0h, accA0);
    upk2(x1l, x1h, accA1);
    out[base + t]          = fmaf(x0l + x0h, invA, aA);
    out[PLANE + base + t]  = fmaf(x1l + x1h, invA, bA);

    upk2(x0l, x0h, accB0);
    upk2(x1l, x1h, accB1);
    out[base + t + 128]         = fmaf(x0l + x0h, invB, aB);
    out[PLANE + base + t + 128] = fmaf(x1l + x1h, invB, bB);
}

extern "C" void kernel_launch(void* const* d_in, const int* in_sizes, int n_in,
                              void* d_out, int out_size)
{
    (void)in_sizes; (void)n_in; (void)out_size;
    channel_attn_kernel<<<BH_TOTAL / 2, 256>>>(
        (const float*)d_in[0], (const float*)d_in[1],
        (const float*)d_in[2], (const float*)d_in[3],
        (const float*)d_in[4], (const float*)d_in[5],
        (const float*)d_in[6], (const float*)d_in[7],
        (float*)d_out);
}